// round 14
// baseline (speedup 1.0000x reference)
#include <cuda_runtime.h>
#include <cuda_fp16.h>
#include <cstdint>

// ---------------------------------------------------------------------------
// SelectiveSSM on GB300 (base sm_103 target => mma.sync path).
// R14 over passing R13 (545.3 us):
//   1. GEMM CTA tile 256x128 (8 warps of 64x64, 256 thr, 1 CTA/SM, 4x24KB
//      pipeline) — halves L2 staged bytes per MAC; model says L2 delivery
//      (770 cyc/ktile) was binding over tensor (512), this flips it.
//   2. GEMM2 writes proj as fp16; combine reads __half.
//   3. Launch order: weight preps just-before-use (also aims ncu at a GEMM).
// Elementwise/prep kernels byte-identical to R13.
// ---------------------------------------------------------------------------

#define D_STATE 16
#define BSZ     2
#define LSEQ    4096
#define DMODEL  1024
#define DINNER  2048
#define NROWS   (BSZ * LSEQ)            // 8192
#define NXZ     (2 * DINNER)            // 4096
#define NPROJ   (2 * D_STATE + DINNER)  // 2080
#define NPROJ_PAD 2176                  // 17 * 128

// Scratch (device globals: allocation-free)
__device__ __half g_xz[NROWS * (size_t)NXZ];       // GEMM1 out (fp16)
__device__ __half g_proj[NROWS * (size_t)NPROJ];   // GEMM2 out (fp16)
// fragment-major fp16 operands (u32 = packed half2)
__device__ uint32_t g_xf[NROWS * (size_t)DMODEL / 2];        // x       (A, GEMM1)
__device__ uint32_t g_winf[NXZ * (size_t)DMODEL / 2];        // W_in    (B, GEMM1)
__device__ uint32_t g_xcf[NROWS * (size_t)DINNER / 2];       // xc      (A, GEMM2)
__device__ uint32_t g_wxpf[NPROJ_PAD * (size_t)DINNER / 2];  // W_xproj (B, GEMM2)
__device__ uint32_t g_yf[NROWS * (size_t)DINNER / 2];        // y       (A, GEMM3)
__device__ uint32_t g_woutf[DMODEL * (size_t)DINNER / 2];    // W_out   (B, GEMM3)

// ---------------------------------------------------------------------------
// fp16 fragment layout, per 128(row) x 32(k) tile = 2048 u32 (8 KB).
// A-slot (uint4) at (kstep_in, mtile, lane):
//   r0 = mtile*16 + (lane>>2), c0 = kstep_in*16 + 2*(lane&3)
//   regs = (r0,c0) (r0+8,c0) (r0,c0+8) (r0+8,c0+8)   [half2 pairs]
// B-slot (uint2): n0 = ntile*8 + (lane>>2); regs = (n0,c0) (n0,c0+8).
// ---------------------------------------------------------------------------

__device__ __forceinline__ uint32_t pack_h2(float lo, float hi) {
    __half2 h = __floats2half2_rn(lo, hi);
    return *reinterpret_cast<uint32_t*>(&h);
}

__device__ __forceinline__ void mma16(float acc[4], const uint32_t a[4], const uint32_t b[2]) {
    asm volatile(
        "mma.sync.aligned.m16n8k16.row.col.f32.f16.f16.f32 "
        "{%0,%1,%2,%3}, {%4,%5,%6,%7}, {%8,%9}, {%0,%1,%2,%3};"
        : "+f"(acc[0]), "+f"(acc[1]), "+f"(acc[2]), "+f"(acc[3])
        : "r"(a[0]), "r"(a[1]), "r"(a[2]), "r"(a[3]), "r"(b[0]), "r"(b[1]));
}

#define CP_ASYNC16(dst_u32, src_ptr) \
    asm volatile("cp.async.cg.shared.global [%0], [%1], 16;" \
                 :: "r"(dst_u32), "l"(src_ptr) : "memory")
#define CP_COMMIT() asm volatile("cp.async.commit_group;" ::: "memory")
#define CP_WAIT0()  asm volatile("cp.async.wait_group 0;" ::: "memory")
#define CP_WAIT1()  asm volatile("cp.async.wait_group 1;" ::: "memory")
#define CP_WAIT2()  asm volatile("cp.async.wait_group 2;" ::: "memory")

__device__ __forceinline__ uint32_t smem_u32a(const void* p) {
    uint32_t a;
    asm("{ .reg .u64 t; cvta.to.shared.u64 t, %1; cvt.u32.u64 %0, t; }"
        : "=r"(a) : "l"(p));
    return a;
}

// ---------------------------------------------------------------------------
// fp16 GEMM: C[M,N] = A[M,K] * B[N,K]^T, fragment-major fp16 operands.
// CTA tile 256x128, BK=32, 256 threads, warp grid 4(m) x 2(n), warp 64x64.
// smem buffer = A0(8K) + A1(8K) + B(8K) = 24 KB; 4 buffers = 96 KB dynamic.
// 1 CTA/SM, 4-stage pipeline (stage-ahead 3, wait_group 2 steady state).
// ---------------------------------------------------------------------------
#define GBUF_U32 6144   // 24 KB per buffer in u32

template<bool HALF_OUT>
__global__ void __launch_bounds__(256, 1)
gemm_f16(const uint32_t* __restrict__ Af, const uint32_t* __restrict__ Bf,
         void* __restrict__ Cv, int M, int N, int KT /* = K/32 */)
{
    extern __shared__ uint32_t smem[];   // 4 x 6144 u32
    const int tid  = threadIdx.x;
    const int lane = tid & 31;
    const int warp = tid >> 5;
    const int wm   = warp >> 1;       // 0..3
    const int wn   = warp & 1;        // 0..1
    const int m0   = blockIdx.y * 256;
    const int n0   = blockIdx.x * 128;

    const uint32_t sb = smem_u32a(smem);
    const uint32_t* At0 = Af + (size_t)(2 * blockIdx.y) * KT * 2048;
    const uint32_t* At1 = At0 + (size_t)KT * 2048;
    const uint32_t* Bt  = Bf + (size_t)blockIdx.x * KT * 2048;

    float acc[4][8][4];
#pragma unroll
    for (int i = 0; i < 4; i++)
#pragma unroll
        for (int j = 0; j < 8; j++)
#pragma unroll
            for (int q = 0; q < 4; q++) acc[i][j][q] = 0.f;

    // ---- prologue: stage tiles 0..2 into buffers 0..2 (stage-ahead 3)
#pragma unroll
    for (int p = 0; p < 3; p++) {
        if (p < KT) {
            const uint32_t boff = (uint32_t)p * (GBUF_U32 * 4u);   // bytes
            const uint32_t* A0 = At0 + (size_t)p * 2048;
            const uint32_t* A1 = At1 + (size_t)p * 2048;
            const uint32_t* Bn = Bt  + (size_t)p * 2048;
#pragma unroll
            for (int i = 0; i < 2; i++) {
                const int s = tid + 256 * i;                        // 0..511
                CP_ASYNC16(sb + boff + (uint32_t)s * 16,            A0 + (size_t)s * 4);
                CP_ASYNC16(sb + boff + 8192u  + (uint32_t)s * 16,   A1 + (size_t)s * 4);
                CP_ASYNC16(sb + boff + 16384u + (uint32_t)s * 16,   Bn + (size_t)s * 4);
            }
            CP_COMMIT();
        }
    }

    for (int kt = 0; kt < KT; ++kt) {
        const int remaining = KT - 1 - kt;
        if (remaining >= 2)      CP_WAIT2();
        else if (remaining == 1) CP_WAIT1();
        else                     CP_WAIT0();
        __syncthreads();

        if (kt + 3 < KT) {
            const uint32_t boff = (uint32_t)((kt + 3) & 3) * (GBUF_U32 * 4u);
            const uint32_t* A0 = At0 + (size_t)(kt + 3) * 2048;
            const uint32_t* A1 = At1 + (size_t)(kt + 3) * 2048;
            const uint32_t* Bn = Bt  + (size_t)(kt + 3) * 2048;
#pragma unroll
            for (int i = 0; i < 2; i++) {
                const int s = tid + 256 * i;
                CP_ASYNC16(sb + boff + (uint32_t)s * 16,            A0 + (size_t)s * 4);
                CP_ASYNC16(sb + boff + 8192u  + (uint32_t)s * 16,   A1 + (size_t)s * 4);
                CP_ASYNC16(sb + boff + 16384u + (uint32_t)s * 16,   Bn + (size_t)s * 4);
            }
            CP_COMMIT();
        }

        // ---- compute from buffer kt&3 (2 k-steps of 16), warp tile 64x64
        const uint32_t* Asb = smem + (kt & 3) * GBUF_U32 + (wm >> 1) * 2048;
        const uint32_t* Bsb = smem + (kt & 3) * GBUF_U32 + 4096;
#pragma unroll
        for (int ks = 0; ks < 2; ++ks) {
            uint32_t af[4][4];
            uint32_t bf[8][2];
#pragma unroll
            for (int im = 0; im < 4; ++im) {
                const int mt = (wm & 1) * 4 + im;
                const uint4 t = *reinterpret_cast<const uint4*>(
                    &Asb[((((ks << 3) + mt) << 5) + lane) * 4]);
                af[im][0] = t.x; af[im][1] = t.y; af[im][2] = t.z; af[im][3] = t.w;
            }
#pragma unroll
            for (int jn = 0; jn < 8; ++jn) {
                const int nt = wn * 8 + jn;
                const uint2 t = *reinterpret_cast<const uint2*>(
                    &Bsb[((((ks << 4) + nt) << 5) + lane) * 2]);
                bf[jn][0] = t.x; bf[jn][1] = t.y;
            }
#pragma unroll
            for (int im = 0; im < 4; ++im)
#pragma unroll
                for (int jn = 0; jn < 8; ++jn)
                    mma16(acc[im][jn], af[im], bf[jn]);
        }
    }

    // ---- epilogue
    const int g = lane >> 2, t = lane & 3;
#pragma unroll
    for (int im = 0; im < 4; ++im) {
        const int mrow = m0 + wm * 64 + im * 16 + g;
#pragma unroll
        for (int jn = 0; jn < 8; ++jn) {
            const int nb = n0 + wn * 64 + jn * 8;
            if (nb < N) {   // N % 8 == 0 always
                if (HALF_OUT) {
                    __half* C = (__half*)Cv;
                    *reinterpret_cast<__half2*>(&C[(size_t)mrow * N + nb + 2 * t]) =
                        __floats2half2_rn(acc[im][jn][0], acc[im][jn][1]);
                    *reinterpret_cast<__half2*>(&C[(size_t)(mrow + 8) * N + nb + 2 * t]) =
                        __floats2half2_rn(acc[im][jn][2], acc[im][jn][3]);
                } else {
                    float* C = (float*)Cv;
                    float2 v0 = make_float2(acc[im][jn][0], acc[im][jn][1]);
                    float2 v1 = make_float2(acc[im][jn][2], acc[im][jn][3]);
                    *reinterpret_cast<float2*>(&C[(size_t)mrow * N + nb + 2 * t])       = v0;
                    *reinterpret_cast<float2*>(&C[(size_t)(mrow + 8) * N + nb + 2 * t]) = v1;
                }
            }
        }
    }
}

// ---------------------------------------------------------------------------
// Preps: slot-per-thread, coalesced STG.128 / STG.64 (unchanged from R13)
// ---------------------------------------------------------------------------
__global__ void __launch_bounds__(256)
prep_frag_a(const float* __restrict__ src, uint32_t* __restrict__ dst, int M, int K)
{
    const int w    = blockIdx.x * 8 + (threadIdx.x >> 5);
    const int lane = threadIdx.x & 31;
    const int TC   = K >> 5;
    const int tile = w >> 4;
    const int slab = w & 15;
    const int tr = tile / TC, tc = tile - tr * TC;
    const int ksin = slab >> 3, mtile = slab & 7;
    const int r0 = tr * 128 + mtile * 16 + (lane >> 2);
    const int c0 = tc * 32 + ksin * 16 + 2 * (lane & 3);

    const float2 v0 = *reinterpret_cast<const float2*>(&src[(size_t)r0 * K + c0]);
    const float2 v1 = *reinterpret_cast<const float2*>(&src[(size_t)(r0 + 8) * K + c0]);
    const float2 v2 = *reinterpret_cast<const float2*>(&src[(size_t)r0 * K + c0 + 8]);
    const float2 v3 = *reinterpret_cast<const float2*>(&src[(size_t)(r0 + 8) * K + c0 + 8]);
    uint4 o;
    o.x = pack_h2(v0.x, v0.y);
    o.y = pack_h2(v1.x, v1.y);
    o.z = pack_h2(v2.x, v2.y);
    o.w = pack_h2(v3.x, v3.y);
    *reinterpret_cast<uint4*>(dst + (size_t)tile * 2048 + slab * 128 + lane * 4) = o;
}

__global__ void __launch_bounds__(256)
prep_frag_b(const float* __restrict__ src, uint32_t* __restrict__ dst,
            int Nr, int K, int Npad)
{
    const int w    = blockIdx.x * 8 + (threadIdx.x >> 5);
    const int lane = threadIdx.x & 31;
    const int TC   = K >> 5;
    const int tile = w >> 5;
    const int slab = w & 31;
    const int tr = tile / TC, tc = tile - tr * TC;
    const int ksin = slab >> 4, ntile = slab & 15;
    const int n0 = tr * 128 + ntile * 8 + (lane >> 2);
    const int c0 = tc * 32 + ksin * 16 + 2 * (lane & 3);

    float2 v0 = make_float2(0.f, 0.f), v1 = make_float2(0.f, 0.f);
    if (n0 < Nr) {
        v0 = *reinterpret_cast<const float2*>(&src[(size_t)n0 * K + c0]);
        v1 = *reinterpret_cast<const float2*>(&src[(size_t)n0 * K + c0 + 8]);
    }
    uint2 o;
    o.x = pack_h2(v0.x, v0.y);
    o.y = pack_h2(v1.x, v1.y);
    *reinterpret_cast<uint2*>(dst + (size_t)tile * 2048 + slab * 64 + lane * 2) = o;
}

// ---------------------------------------------------------------------------
// Elementwise (conv unchanged from R13; combine reads fp16 proj)
// ---------------------------------------------------------------------------
__device__ __forceinline__ float siluf(float v)     { return v / (1.f + expf(-v)); }
__device__ __forceinline__ float softplusf(float v) { return fmaxf(v, 0.f) + log1pf(expf(-fabsf(v))); }

__device__ __forceinline__ uint32_t conv_pair(
    const __half* __restrict__ xz, const float* __restrict__ cw,
    const float* __restrict__ cb, int row, int c)
{
    float a = cb[c], b = cb[c + 1];
    const int l = row & (LSEQ - 1);
#pragma unroll
    for (int k = 0; k < 4; k++) {
        if (l + k - 3 >= 0) {
            const float2 f = __half22float2(
                *reinterpret_cast<const __half2*>(&xz[(size_t)(row + k - 3) * NXZ + c]));
            a = fmaf(cw[c * 4 + k],       f.x, a);
            b = fmaf(cw[(c + 1) * 4 + k], f.y, b);
        }
    }
    return pack_h2(siluf(a), siluf(b));
}

__global__ void __launch_bounds__(256)
conv_silu_kernel(const __half* __restrict__ xz, const float* __restrict__ cw,
                 const float* __restrict__ cb, uint32_t* __restrict__ xcf)
{
    const int w    = blockIdx.x * 8 + (threadIdx.x >> 5);
    const int lane = threadIdx.x & 31;
    const int tile  = w >> 10;
    const int kstep = (w >> 3) & 127;
    const int mtile = w & 7;
    const int r0 = tile * 128 + mtile * 16 + (lane >> 2);
    const int c0 = kstep * 16 + 2 * (lane & 3);

    uint4 o;
    o.x = conv_pair(xz, cw, cb, r0,     c0);
    o.y = conv_pair(xz, cw, cb, r0 + 8, c0);
    o.z = conv_pair(xz, cw, cb, r0,     c0 + 8);
    o.w = conv_pair(xz, cw, cb, r0 + 8, c0 + 8);

    uint32_t* d = xcf + (size_t)(tile * (DINNER >> 5) + (kstep >> 1)) * 2048
                      + (((kstep & 1) * 8 + mtile) * 32 + lane) * 4;
    *reinterpret_cast<uint4*>(d) = o;
}

__device__ __forceinline__ uint32_t comb_pair(
    const __half* __restrict__ xz, const __half* __restrict__ proj,
    const float* __restrict__ D, int row, int c, float bc, uint32_t xc2)
{
    const float2 dp = __half22float2(
        *reinterpret_cast<const __half2*>(&proj[(size_t)row * NPROJ + 2 * D_STATE + c]));
    const float2 z  = __half22float2(
        *reinterpret_cast<const __half2*>(&xz[(size_t)row * NXZ + DINNER + c]));
    const float2 Dv = *reinterpret_cast<const float2*>(&D[c]);
    const __half2 xh = *reinterpret_cast<const __half2*>(&xc2);
    const float y0 = (softplusf(dp.x) * bc + Dv.x) * __low2float(xh)  * siluf(z.x);
    const float y1 = (softplusf(dp.y) * bc + Dv.y) * __high2float(xh) * siluf(z.y);
    return pack_h2(y0, y1);
}

__global__ void __launch_bounds__(256)
combine_kernel(const __half* __restrict__ xz, const uint32_t* __restrict__ xcf,
               const __half* __restrict__ proj, const float* __restrict__ D,
               uint32_t* __restrict__ yf)
{
    __shared__ float sbc[128];
    const int tile = blockIdx.x >> 4;
    const int kgrp = blockIdx.x & 15;
    const int tid  = threadIdx.x;

    if (tid < 128) {
        const __half* pr = proj + (size_t)(tile * 128 + tid) * NPROJ;
        float v = 0.f;
#pragma unroll
        for (int s = 0; s < D_STATE; s++)
            v = fmaf(__half2float(pr[s]), __half2float(pr[D_STATE + s]), v);
        sbc[tid] = v;
    }
    __syncthreads();

    const int warp = tid >> 5, lane = tid & 31;
#pragma unroll
    for (int i = 0; i < 8; i++) {
        const int slab  = warp * 8 + i;
        const int ks    = kgrp * 8 + (slab >> 3);
        const int mtile = slab & 7;
        const int rr0   = mtile * 16 + (lane >> 2);
        const int r0    = tile * 128 + rr0;
        const int c0    = ks * 16 + 2 * (lane & 3);
        const size_t base = (size_t)(tile * (DINNER >> 5) + (ks >> 1)) * 2048
                          + (((ks & 1) * 8 + mtile) * 32 + lane) * 4;
        const uint4 xin = *reinterpret_cast<const uint4*>(xcf + base);
        const float bc0 = sbc[rr0], bc1 = sbc[rr0 + 8];
        uint4 o;
        o.x = comb_pair(xz, proj, D, r0,     c0,     bc0, xin.x);
        o.y = comb_pair(xz, proj, D, r0 + 8, c0,     bc1, xin.y);
        o.z = comb_pair(xz, proj, D, r0,     c0 + 8, bc0, xin.z);
        o.w = comb_pair(xz, proj, D, r0 + 8, c0 + 8, bc1, xin.w);
        *reinterpret_cast<uint4*>(yf + base) = o;
    }
}

// ---------------------------------------------------------------------------
// Launch
// ---------------------------------------------------------------------------
extern "C" void kernel_launch(void* const* d_in, const int* in_sizes, int n_in,
                              void* d_out, int out_size)
{
    const float* x      = (const float*)d_in[0];
    const float* W_in   = (const float*)d_in[1];
    const float* conv_w = (const float*)d_in[2];
    const float* conv_b = (const float*)d_in[3];
    const float* W_xp   = (const float*)d_in[4];
    const float* D      = (const float*)d_in[5];
    const float* W_out  = (const float*)d_in[6];
    float* out = (float*)d_out;

    void *p_xz, *p_proj, *p_xf, *p_winf, *p_xcf, *p_wxpf, *p_yf, *p_woutf;
    cudaGetSymbolAddress(&p_xz,    g_xz);
    cudaGetSymbolAddress(&p_proj,  g_proj);
    cudaGetSymbolAddress(&p_xf,    g_xf);
    cudaGetSymbolAddress(&p_winf,  g_winf);
    cudaGetSymbolAddress(&p_xcf,   g_xcf);
    cudaGetSymbolAddress(&p_wxpf,  g_wxpf);
    cudaGetSymbolAddress(&p_yf,    g_yf);
    cudaGetSymbolAddress(&p_woutf, g_woutf);

    cudaFuncSetAttribute(gemm_f16<true>,  cudaFuncAttributeMaxDynamicSharedMemorySize, 98304);
    cudaFuncSetAttribute(gemm_f16<false>, cudaFuncAttributeMaxDynamicSharedMemorySize, 98304);

    // Preps just-before-use (dependency-safe; also aims ncu -s at a GEMM)
    prep_frag_a<<<4096, 256>>>(x, (uint32_t*)p_xf, NROWS, DMODEL);
    prep_frag_b<<<4096, 256>>>(W_in, (uint32_t*)p_winf, NXZ, DMODEL, NXZ);

    // GEMM1: xz = x @ W_in^T   (8192 x 4096 x 1024), fp16 output
    gemm_f16<true><<<dim3(NXZ / 128, NROWS / 256), 256, 98304>>>(
        (const uint32_t*)p_xf, (const uint32_t*)p_winf, p_xz,
        NROWS, NXZ, DMODEL / 32);

    // conv + SiLU -> xc (fragment layout)
    conv_silu_kernel<<<8192, 256>>>(
        (const __half*)p_xz, conv_w, conv_b, (uint32_t*)p_xcf);

    prep_frag_b<<<4352, 256>>>(W_xp, (uint32_t*)p_wxpf, NPROJ, DINNER, NPROJ_PAD);

    // GEMM2: proj = xc @ W_xproj^T  (8192 x 2080 x 2048), fp16 output
    gemm_f16<true><<<dim3(NPROJ_PAD / 128, NROWS / 256), 256, 98304>>>(
        (const uint32_t*)p_xcf, (const uint32_t*)p_wxpf, p_proj,
        NROWS, NPROJ, DINNER / 32);

    // combine -> y (fragment layout)
    combine_kernel<<<1024, 256>>>(
        (const __half*)p_xz, (const uint32_t*)p_xcf, (const __half*)p_proj, D,
        (uint32_t*)p_yf);

    prep_frag_b<<<2048, 256>>>(W_out, (uint32_t*)p_woutf, DMODEL, DINNER, DMODEL);

    // GEMM3: out = y @ W_out^T   (8192 x 1024 x 2048), fp32 output
    gemm_f16<false><<<dim3(DMODEL / 128, NROWS / 256), 256, 98304>>>(
        (const uint32_t*)p_yf, (const uint32_t*)p_woutf, out,
        NROWS, DMODEL, DINNER / 32);
}

// round 15
// speedup vs baseline: 1.2175x; 1.2175x over previous
#include <cuda_runtime.h>
#include <cuda_fp16.h>
#include <cstdint>

// ---------------------------------------------------------------------------
// SelectiveSSM on GB300 (base sm_103 target => mma.sync path).
// R15: GEMM reverted to the proven R13 config (128x128 CTA, 2 CTA/SM,
// 4-stage cp.async) — the 256x128/1-CTA variant regressed twice (R8, R14).
// Kept from R14: fp16 proj (GEMM2 HALF_OUT). New: conv_silu stages its
// 131-row x 16-ch input slab through smem (coalesced loads, conflict-free
// reads) to fix the measured L1=83.9% sector explosion.
// ---------------------------------------------------------------------------

#define D_STATE 16
#define BSZ     2
#define LSEQ    4096
#define DMODEL  1024
#define DINNER  2048
#define NROWS   (BSZ * LSEQ)            // 8192
#define NXZ     (2 * DINNER)            // 4096
#define NPROJ   (2 * D_STATE + DINNER)  // 2080
#define NPROJ_PAD 2176                  // 17 * 128

// Scratch (device globals: allocation-free)
__device__ __half g_xz[NROWS * (size_t)NXZ];       // GEMM1 out (fp16)
__device__ __half g_proj[NROWS * (size_t)NPROJ];   // GEMM2 out (fp16)
// fragment-major fp16 operands (u32 = packed half2)
__device__ uint32_t g_xf[NROWS * (size_t)DMODEL / 2];
__device__ uint32_t g_winf[NXZ * (size_t)DMODEL / 2];
__device__ uint32_t g_xcf[NROWS * (size_t)DINNER / 2];
__device__ uint32_t g_wxpf[NPROJ_PAD * (size_t)DINNER / 2];
__device__ uint32_t g_yf[NROWS * (size_t)DINNER / 2];
__device__ uint32_t g_woutf[DMODEL * (size_t)DINNER / 2];

// ---------------------------------------------------------------------------
// fp16 fragment layout, per 128(row) x 32(k) tile = 2048 u32 (8 KB).
// A-slot (uint4) at (ksin, mtile, lane): r0 = mtile*16 + (lane>>2),
//   c0 = ksin*16 + 2*(lane&3); regs = (r0,c0)(r0+8,c0)(r0,c0+8)(r0+8,c0+8).
// B-slot (uint2): n0 = ntile*8 + (lane>>2); regs = (n0,c0)(n0,c0+8).
// ---------------------------------------------------------------------------

__device__ __forceinline__ uint32_t pack_h2(float lo, float hi) {
    __half2 h = __floats2half2_rn(lo, hi);
    return *reinterpret_cast<uint32_t*>(&h);
}

__device__ __forceinline__ void mma16(float acc[4], const uint32_t a[4], const uint32_t b[2]) {
    asm volatile(
        "mma.sync.aligned.m16n8k16.row.col.f32.f16.f16.f32 "
        "{%0,%1,%2,%3}, {%4,%5,%6,%7}, {%8,%9}, {%0,%1,%2,%3};"
        : "+f"(acc[0]), "+f"(acc[1]), "+f"(acc[2]), "+f"(acc[3])
        : "r"(a[0]), "r"(a[1]), "r"(a[2]), "r"(a[3]), "r"(b[0]), "r"(b[1]));
}

#define CP_ASYNC16(dst_u32, src_ptr) \
    asm volatile("cp.async.cg.shared.global [%0], [%1], 16;" \
                 :: "r"(dst_u32), "l"(src_ptr) : "memory")
#define CP_COMMIT() asm volatile("cp.async.commit_group;" ::: "memory")
#define CP_WAIT0()  asm volatile("cp.async.wait_group 0;" ::: "memory")
#define CP_WAIT1()  asm volatile("cp.async.wait_group 1;" ::: "memory")
#define CP_WAIT2()  asm volatile("cp.async.wait_group 2;" ::: "memory")

__device__ __forceinline__ uint32_t smem_u32a(const void* p) {
    uint32_t a;
    asm("{ .reg .u64 t; cvta.to.shared.u64 t, %1; cvt.u32.u64 %0, t; }"
        : "=r"(a) : "l"(p));
    return a;
}

// ---------------------------------------------------------------------------
// fp16 GEMM — byte-identical to passing R13 (plus HALF_OUT template).
// CTA 128x128, BK=32, 128 threads, warp grid 2x2, warp tile 64x64.
// smem: 4 buffers x 16 KB = 64 KB dynamic. 2 CTA/SM. 4-stage pipeline.
// ---------------------------------------------------------------------------
template<bool HALF_OUT>
__global__ void __launch_bounds__(128, 2)
gemm_f16(const uint32_t* __restrict__ Af, const uint32_t* __restrict__ Bf,
         void* __restrict__ Cv, int M, int N, int KT /* = K/32 */)
{
    extern __shared__ uint32_t smem[];   // 4 x 4096 u32
    const int tid  = threadIdx.x;
    const int lane = tid & 31;
    const int warp = tid >> 5;
    const int wm   = warp >> 1;       // 0..1
    const int wn   = warp & 1;        // 0..1
    const int m0   = blockIdx.y * 128;
    const int n0   = blockIdx.x * 128;

    const uint32_t sb = smem_u32a(smem);
    const uint32_t* At = Af + (size_t)blockIdx.y * KT * 2048;
    const uint32_t* Bt = Bf + (size_t)blockIdx.x * KT * 2048;

    float acc[4][8][4];
#pragma unroll
    for (int i = 0; i < 4; i++)
#pragma unroll
        for (int j = 0; j < 8; j++)
#pragma unroll
            for (int q = 0; q < 4; q++) acc[i][j][q] = 0.f;

    // ---- prologue: stage tiles 0..2 into buffers 0..2 (stage-ahead 3)
#pragma unroll
    for (int p = 0; p < 3; p++) {
        if (p < KT) {
            const uint32_t boff = (uint32_t)p * 16384u;
            const uint32_t* An = At + (size_t)p * 2048;
            const uint32_t* Bn = Bt + (size_t)p * 2048;
#pragma unroll
            for (int i = 0; i < 4; i++) {
                const int s = tid + 128 * i;
                CP_ASYNC16(sb + boff + (uint32_t)s * 16,         An + (size_t)s * 4);
                CP_ASYNC16(sb + boff + 8192u + (uint32_t)s * 16, Bn + (size_t)s * 4);
            }
            CP_COMMIT();
        }
    }

    for (int kt = 0; kt < KT; ++kt) {
        const int remaining = KT - 1 - kt;
        if (remaining >= 2)      CP_WAIT2();
        else if (remaining == 1) CP_WAIT1();
        else                     CP_WAIT0();
        __syncthreads();

        if (kt + 3 < KT) {
            const uint32_t boff = (uint32_t)((kt + 3) & 3) * 16384u;
            const uint32_t* An = At + (size_t)(kt + 3) * 2048;
            const uint32_t* Bn = Bt + (size_t)(kt + 3) * 2048;
#pragma unroll
            for (int i = 0; i < 4; i++) {
                const int s = tid + 128 * i;
                CP_ASYNC16(sb + boff + (uint32_t)s * 16,         An + (size_t)s * 4);
                CP_ASYNC16(sb + boff + 8192u + (uint32_t)s * 16, Bn + (size_t)s * 4);
            }
            CP_COMMIT();
        }

        const uint32_t* Asb = smem + (kt & 3) * 4096;
        const uint32_t* Bsb = Asb + 2048;
#pragma unroll
        for (int ks = 0; ks < 2; ++ks) {
            uint32_t af[4][4];
            uint32_t bf[8][2];
#pragma unroll
            for (int im = 0; im < 4; ++im) {
                const int mt = wm * 4 + im;
                const uint4 t = *reinterpret_cast<const uint4*>(
                    &Asb[((((ks << 3) + mt) << 5) + lane) * 4]);
                af[im][0] = t.x; af[im][1] = t.y; af[im][2] = t.z; af[im][3] = t.w;
            }
#pragma unroll
            for (int jn = 0; jn < 8; ++jn) {
                const int nt = wn * 8 + jn;
                const uint2 t = *reinterpret_cast<const uint2*>(
                    &Bsb[((((ks << 4) + nt) << 5) + lane) * 2]);
                bf[jn][0] = t.x; bf[jn][1] = t.y;
            }
#pragma unroll
            for (int im = 0; im < 4; ++im)
#pragma unroll
                for (int jn = 0; jn < 8; ++jn)
                    mma16(acc[im][jn], af[im], bf[jn]);
        }
    }

    // ---- epilogue
    const int g = lane >> 2, t = lane & 3;
#pragma unroll
    for (int im = 0; im < 4; ++im) {
        const int mrow = m0 + wm * 64 + im * 16 + g;
#pragma unroll
        for (int jn = 0; jn < 8; ++jn) {
            const int nb = n0 + wn * 64 + jn * 8;
            if (nb < N) {
                if (HALF_OUT) {
                    __half* C = (__half*)Cv;
                    *reinterpret_cast<__half2*>(&C[(size_t)mrow * N + nb + 2 * t]) =
                        __floats2half2_rn(acc[im][jn][0], acc[im][jn][1]);
                    *reinterpret_cast<__half2*>(&C[(size_t)(mrow + 8) * N + nb + 2 * t]) =
                        __floats2half2_rn(acc[im][jn][2], acc[im][jn][3]);
                } else {
                    float* C = (float*)Cv;
                    float2 v0 = make_float2(acc[im][jn][0], acc[im][jn][1]);
                    float2 v1 = make_float2(acc[im][jn][2], acc[im][jn][3]);
                    *reinterpret_cast<float2*>(&C[(size_t)mrow * N + nb + 2 * t])       = v0;
                    *reinterpret_cast<float2*>(&C[(size_t)(mrow + 8) * N + nb + 2 * t]) = v1;
                }
            }
        }
    }
}

// ---------------------------------------------------------------------------
// Preps (unchanged from R13): slot-per-thread, coalesced stores
// ---------------------------------------------------------------------------
__global__ void __launch_bounds__(256)
prep_frag_a(const float* __restrict__ src, uint32_t* __restrict__ dst, int M, int K)
{
    const int w    = blockIdx.x * 8 + (threadIdx.x >> 5);
    const int lane = threadIdx.x & 31;
    const int TC   = K >> 5;
    const int tile = w >> 4;
    const int slab = w & 15;
    const int tr = tile / TC, tc = tile - tr * TC;
    const int ksin = slab >> 3, mtile = slab & 7;
    const int r0 = tr * 128 + mtile * 16 + (lane >> 2);
    const int c0 = tc * 32 + ksin * 16 + 2 * (lane & 3);

    const float2 v0 = *reinterpret_cast<const float2*>(&src[(size_t)r0 * K + c0]);
    const float2 v1 = *reinterpret_cast<const float2*>(&src[(size_t)(r0 + 8) * K + c0]);
    const float2 v2 = *reinterpret_cast<const float2*>(&src[(size_t)r0 * K + c0 + 8]);
    const float2 v3 = *reinterpret_cast<const float2*>(&src[(size_t)(r0 + 8) * K + c0 + 8]);
    uint4 o;
    o.x = pack_h2(v0.x, v0.y);
    o.y = pack_h2(v1.x, v1.y);
    o.z = pack_h2(v2.x, v2.y);
    o.w = pack_h2(v3.x, v3.y);
    *reinterpret_cast<uint4*>(dst + (size_t)tile * 2048 + slab * 128 + lane * 4) = o;
}

__global__ void __launch_bounds__(256)
prep_frag_b(const float* __restrict__ src, uint32_t* __restrict__ dst,
            int Nr, int K, int Npad)
{
    const int w    = blockIdx.x * 8 + (threadIdx.x >> 5);
    const int lane = threadIdx.x & 31;
    const int TC   = K >> 5;
    const int tile = w >> 5;
    const int slab = w & 31;
    const int tr = tile / TC, tc = tile - tr * TC;
    const int ksin = slab >> 4, ntile = slab & 15;
    const int n0 = tr * 128 + ntile * 8 + (lane >> 2);
    const int c0 = tc * 32 + ksin * 16 + 2 * (lane & 3);

    float2 v0 = make_float2(0.f, 0.f), v1 = make_float2(0.f, 0.f);
    if (n0 < Nr) {
        v0 = *reinterpret_cast<const float2*>(&src[(size_t)n0 * K + c0]);
        v1 = *reinterpret_cast<const float2*>(&src[(size_t)n0 * K + c0 + 8]);
    }
    uint2 o;
    o.x = pack_h2(v0.x, v0.y);
    o.y = pack_h2(v1.x, v1.y);
    *reinterpret_cast<uint2*>(dst + (size_t)tile * 2048 + slab * 64 + lane * 2) = o;
}

// ---------------------------------------------------------------------------
// Elementwise
// ---------------------------------------------------------------------------
__device__ __forceinline__ float siluf(float v)     { return v / (1.f + expf(-v)); }
__device__ __forceinline__ float softplusf(float v) { return fmaxf(v, 0.f) + log1pf(expf(-fabsf(v))); }

// conv+silu, smem-staged.
// Block = one (128-row tile, 16-channel kstep). smem slab: 131 rows x 16 ch
// fp16, row stride 9 u32 (36 B) for conflict-free taps.
// smem row s holds global row (tile*128 + s - 3); s<3 is the halo, zeroed
// when the tile starts a batch (tile*128 % 4096 == 0).
__global__ void __launch_bounds__(256)
conv_silu_kernel(const __half* __restrict__ xz, const float* __restrict__ cw,
                 const float* __restrict__ cb, uint32_t* __restrict__ xcf)
{
    __shared__ uint32_t sx[131 * 9];
    const int tid   = threadIdx.x;
    const int tile  = blockIdx.x >> 7;          // 0..63
    const int kstep = blockIdx.x & 127;         // 16-channel step
    const int base_row = tile * 128;
    const bool batch_start = (base_row & (LSEQ - 1)) == 0;

    // cooperative load: 131 rows x 8 u32 (32 B/row of fp16 channels)
    for (int i = tid; i < 131 * 8; i += 256) {
        const int s  = i >> 3;          // smem row
        const int wd = i & 7;           // u32 word within row
        uint32_t v = 0u;
        const int g = base_row + s - 3;
        if (s >= 3 || !batch_start) {
            v = *reinterpret_cast<const uint32_t*>(
                &xz[(size_t)g * NXZ + kstep * 16 + wd * 2]);
        }
        sx[s * 9 + wd] = v;
    }
    __syncthreads();

    // compute: one uint4 fragment slot per thread (8 warps = 8 mtiles)
    const int warp = tid >> 5, lane = tid & 31;
    const int mtile = warp;
    const int rr0 = mtile * 16 + (lane >> 2);   // row offset in tile (0..127)
    const int cl  = 2 * (lane & 3);             // local channel (0..7)
    const int cg  = kstep * 16 + cl;            // global channel base

    // weights for 4 channels (cl, cl+1, cl+8, cl+9), 4 taps each
    float w0[4], w1[4], w2[4], w3[4], bias0, bias1, bias2, bias3;
    bias0 = cb[cg]; bias1 = cb[cg + 1]; bias2 = cb[cg + 8]; bias3 = cb[cg + 9];
#pragma unroll
    for (int k = 0; k < 4; k++) {
        w0[k] = cw[(cg + 0) * 4 + k];
        w1[k] = cw[(cg + 1) * 4 + k];
        w2[k] = cw[(cg + 8) * 4 + k];
        w3[k] = cw[(cg + 9) * 4 + k];
    }

    uint4 o;
#pragma unroll
    for (int half = 0; half < 2; half++) {      // rows rr0 and rr0+8
        const int r = rr0 + half * 8;
        float a0 = bias0, a1 = bias1, a2 = bias2, a3 = bias3;
#pragma unroll
        for (int k = 0; k < 4; k++) {
            // smem row r+k holds global row base_row + r + k - 3 = R + k - 3
            const float2 f0 = __half22float2(
                *reinterpret_cast<const __half2*>(&sx[(r + k) * 9 + (cl >> 1)]));
            const float2 f1 = __half22float2(
                *reinterpret_cast<const __half2*>(&sx[(r + k) * 9 + (cl >> 1) + 4]));
            a0 = fmaf(w0[k], f0.x, a0);
            a1 = fmaf(w1[k], f0.y, a1);
            a2 = fmaf(w2[k], f1.x, a2);
            a3 = fmaf(w3[k], f1.y, a3);
        }
        const uint32_t lo = pack_h2(siluf(a0), siluf(a1));
        const uint32_t hi = pack_h2(siluf(a2), siluf(a3));
        if (half == 0) { o.x = lo; o.z = hi; }
        else           { o.y = lo; o.w = hi; }
    }

    uint32_t* d = xcf + (size_t)(tile * (DINNER >> 5) + (kstep >> 1)) * 2048
                      + (((kstep & 1) * 8 + mtile) * 32 + lane) * 4;
    *reinterpret_cast<uint4*>(d) = o;
}

// combine (unchanged from R14: fp16 proj)
__device__ __forceinline__ uint32_t comb_pair(
    const __half* __restrict__ xz, const __half* __restrict__ proj,
    const float* __restrict__ D, int row, int c, float bc, uint32_t xc2)
{
    const float2 dp = __half22float2(
        *reinterpret_cast<const __half2*>(&proj[(size_t)row * NPROJ + 2 * D_STATE + c]));
    const float2 z  = __half22float2(
        *reinterpret_cast<const __half2*>(&xz[(size_t)row * NXZ + DINNER + c]));
    const float2 Dv = *reinterpret_cast<const float2*>(&D[c]);
    const __half2 xh = *reinterpret_cast<const __half2*>(&xc2);
    const float y0 = (softplusf(dp.x) * bc + Dv.x) * __low2float(xh)  * siluf(z.x);
    const float y1 = (softplusf(dp.y) * bc + Dv.y) * __high2float(xh) * siluf(z.y);
    return pack_h2(y0, y1);
}

__global__ void __launch_bounds__(256)
combine_kernel(const __half* __restrict__ xz, const uint32_t* __restrict__ xcf,
               const __half* __restrict__ proj, const float* __restrict__ D,
               uint32_t* __restrict__ yf)
{
    __shared__ float sbc[128];
    const int tile = blockIdx.x >> 4;
    const int kgrp = blockIdx.x & 15;
    const int tid  = threadIdx.x;

    if (tid < 128) {
        const __half* pr = proj + (size_t)(tile * 128 + tid) * NPROJ;
        float v = 0.f;
#pragma unroll
        for (int s = 0; s < D_STATE; s++)
            v = fmaf(__half2float(pr[s]), __half2float(pr[D_STATE + s]), v);
        sbc[tid] = v;
    }
    __syncthreads();

    const int warp = tid >> 5, lane = tid & 31;
#pragma unroll
    for (int i = 0; i < 8; i++) {
        const int slab  = warp * 8 + i;
        const int ks    = kgrp * 8 + (slab >> 3);
        const int mtile = slab & 7;
        const int rr0   = mtile * 16 + (lane >> 2);
        const int r0    = tile * 128 + rr0;
        const int c0    = ks * 16 + 2 * (lane & 3);
        const size_t base = (size_t)(tile * (DINNER >> 5) + (ks >> 1)) * 2048
                          + (((ks & 1) * 8 + mtile) * 32 + lane) * 4;
        const uint4 xin = *reinterpret_cast<const uint4*>(xcf + base);
        const float bc0 = sbc[rr0], bc1 = sbc[rr0 + 8];
        uint4 o;
        o.x = comb_pair(xz, proj, D, r0,     c0,     bc0, xin.x);
        o.y = comb_pair(xz, proj, D, r0 + 8, c0,     bc1, xin.y);
        o.z = comb_pair(xz, proj, D, r0,     c0 + 8, bc0, xin.z);
        o.w = comb_pair(xz, proj, D, r0 + 8, c0 + 8, bc1, xin.w);
        *reinterpret_cast<uint4*>(yf + base) = o;
    }
}

// ---------------------------------------------------------------------------
// Launch
// ---------------------------------------------------------------------------
extern "C" void kernel_launch(void* const* d_in, const int* in_sizes, int n_in,
                              void* d_out, int out_size)
{
    const float* x      = (const float*)d_in[0];
    const float* W_in   = (const float*)d_in[1];
    const float* conv_w = (const float*)d_in[2];
    const float* conv_b = (const float*)d_in[3];
    const float* W_xp   = (const float*)d_in[4];
    const float* D      = (const float*)d_in[5];
    const float* W_out  = (const float*)d_in[6];
    float* out = (float*)d_out;

    void *p_xz, *p_proj, *p_xf, *p_winf, *p_xcf, *p_wxpf, *p_yf, *p_woutf;
    cudaGetSymbolAddress(&p_xz,    g_xz);
    cudaGetSymbolAddress(&p_proj,  g_proj);
    cudaGetSymbolAddress(&p_xf,    g_xf);
    cudaGetSymbolAddress(&p_winf,  g_winf);
    cudaGetSymbolAddress(&p_xcf,   g_xcf);
    cudaGetSymbolAddress(&p_wxpf,  g_wxpf);
    cudaGetSymbolAddress(&p_yf,    g_yf);
    cudaGetSymbolAddress(&p_woutf, g_woutf);

    cudaFuncSetAttribute(gemm_f16<true>,  cudaFuncAttributeMaxDynamicSharedMemorySize, 65536);
    cudaFuncSetAttribute(gemm_f16<false>, cudaFuncAttributeMaxDynamicSharedMemorySize, 65536);

    // Preps just-before-use
    prep_frag_a<<<4096, 256>>>(x, (uint32_t*)p_xf, NROWS, DMODEL);
    prep_frag_b<<<4096, 256>>>(W_in, (uint32_t*)p_winf, NXZ, DMODEL, NXZ);

    // GEMM1: xz = x @ W_in^T   (8192 x 4096 x 1024), fp16 output
    gemm_f16<true><<<dim3(NXZ / 128, NROWS / 128), 128, 65536>>>(
        (const uint32_t*)p_xf, (const uint32_t*)p_winf, p_xz,
        NROWS, NXZ, DMODEL / 32);

    // conv + SiLU -> xc (fragment layout), smem-staged: 64 tiles x 128 ksteps
    conv_silu_kernel<<<8192, 256>>>(
        (const __half*)p_xz, conv_w, conv_b, (uint32_t*)p_xcf);

    prep_frag_b<<<4352, 256>>>(W_xp, (uint32_t*)p_wxpf, NPROJ, DINNER, NPROJ_PAD);

    // GEMM2: proj = xc @ W_xproj^T  (8192 x 2080 x 2048), fp16 output
    gemm_f16<true><<<dim3(NPROJ_PAD / 128, NROWS / 128), 128, 65536>>>(
        (const uint32_t*)p_xcf, (const uint32_t*)p_wxpf, p_proj,
        NROWS, NPROJ, DINNER / 32);

    // combine -> y (fragment layout)
    combine_kernel<<<1024, 256>>>(
        (const __half*)p_xz, (const uint32_t*)p_xcf, (const __half*)p_proj, D,
        (uint32_t*)p_yf);

    prep_frag_b<<<2048, 256>>>(W_out, (uint32_t*)p_woutf, DMODEL, DINNER, DMODEL);

    // GEMM3: out = y @ W_out^T   (8192 x 1024 x 2048), fp32 output
    gemm_f16<false><<<dim3(DMODEL / 128, NROWS / 128), 128, 65536>>>(
        (const uint32_t*)p_yf, (const uint32_t*)p_woutf, out,
        NROWS, DMODEL, DINNER / 32);
}

// round 16
// speedup vs baseline: 1.2349x; 1.0143x over previous
#include <cuda_runtime.h>
#include <cuda_fp16.h>
#include <cstdint>

// ---------------------------------------------------------------------------
// SelectiveSSM on GB300 (base sm_103 target => mma.sync path).
// R16 over passing R15 (531.2 us):
//   1. GEMM BK=64 (3-stage, 32KB buffers, 96KB dynamic, still 128x128 CTA /
//      2 CTA/SM / 64x64 warp tiles) — halves barrier/wait boundaries.
//   2. conv_silu: 2 ksteps (32 ch) per block, uint4 slab loads, stride-20
//      smem — halves block/barrier/halo overhead (conv was issue-bound).
// Preps/combine byte-identical to R15.
// ---------------------------------------------------------------------------

#define D_STATE 16
#define BSZ     2
#define LSEQ    4096
#define DMODEL  1024
#define DINNER  2048
#define NROWS   (BSZ * LSEQ)            // 8192
#define NXZ     (2 * DINNER)            // 4096
#define NPROJ   (2 * D_STATE + DINNER)  // 2080
#define NPROJ_PAD 2176                  // 17 * 128

// Scratch (device globals: allocation-free)
__device__ __half g_xz[NROWS * (size_t)NXZ];       // GEMM1 out (fp16)
__device__ __half g_proj[NROWS * (size_t)NPROJ];   // GEMM2 out (fp16)
// fragment-major fp16 operands (u32 = packed half2)
__device__ uint32_t g_xf[NROWS * (size_t)DMODEL / 2];
__device__ uint32_t g_winf[NXZ * (size_t)DMODEL / 2];
__device__ uint32_t g_xcf[NROWS * (size_t)DINNER / 2];
__device__ uint32_t g_wxpf[NPROJ_PAD * (size_t)DINNER / 2];
__device__ uint32_t g_yf[NROWS * (size_t)DINNER / 2];
__device__ uint32_t g_woutf[DMODEL * (size_t)DINNER / 2];

// ---------------------------------------------------------------------------
// fp16 fragment layout, per 128(row) x 32(k) tile = 2048 u32 (8 KB).
// A-slot (uint4) at (ksin, mtile, lane): r0 = mtile*16 + (lane>>2),
//   c0 = ksin*16 + 2*(lane&3); regs = (r0,c0)(r0+8,c0)(r0,c0+8)(r0+8,c0+8).
// B-slot (uint2): n0 = ntile*8 + (lane>>2); regs = (n0,c0)(n0,c0+8).
// ---------------------------------------------------------------------------

__device__ __forceinline__ uint32_t pack_h2(float lo, float hi) {
    __half2 h = __floats2half2_rn(lo, hi);
    return *reinterpret_cast<uint32_t*>(&h);
}

__device__ __forceinline__ void mma16(float acc[4], const uint32_t a[4], const uint32_t b[2]) {
    asm volatile(
        "mma.sync.aligned.m16n8k16.row.col.f32.f16.f16.f32 "
        "{%0,%1,%2,%3}, {%4,%5,%6,%7}, {%8,%9}, {%0,%1,%2,%3};"
        : "+f"(acc[0]), "+f"(acc[1]), "+f"(acc[2]), "+f"(acc[3])
        : "r"(a[0]), "r"(a[1]), "r"(a[2]), "r"(a[3]), "r"(b[0]), "r"(b[1]));
}

#define CP_ASYNC16(dst_u32, src_ptr) \
    asm volatile("cp.async.cg.shared.global [%0], [%1], 16;" \
                 :: "r"(dst_u32), "l"(src_ptr) : "memory")
#define CP_COMMIT() asm volatile("cp.async.commit_group;" ::: "memory")
#define CP_WAIT0()  asm volatile("cp.async.wait_group 0;" ::: "memory")
#define CP_WAIT1()  asm volatile("cp.async.wait_group 1;" ::: "memory")

__device__ __forceinline__ uint32_t smem_u32a(const void* p) {
    uint32_t a;
    asm("{ .reg .u64 t; cvta.to.shared.u64 t, %1; cvt.u32.u64 %0, t; }"
        : "=r"(a) : "l"(p));
    return a;
}

// ---------------------------------------------------------------------------
// fp16 GEMM: C[M,N] = A[M,K] * B[N,K]^T, fragment-major fp16 operands.
// CTA 128x128, BK=64, 128 threads, warp grid 2x2, warp tile 64x64.
// Buffer = A(2 frag tiles, 16KB) + B(2 frag tiles, 16KB) = 32 KB;
// 3 buffers = 96 KB dynamic; 2 CTA/SM (192 KB). Stage-ahead 2, wait_group 1.
// KT64 = K/64.
// ---------------------------------------------------------------------------
template<bool HALF_OUT>
__global__ void __launch_bounds__(128, 2)
gemm_f16(const uint32_t* __restrict__ Af, const uint32_t* __restrict__ Bf,
         void* __restrict__ Cv, int M, int N, int KT64)
{
    extern __shared__ uint32_t smem[];   // 3 x 8192 u32
    const int tid  = threadIdx.x;
    const int lane = tid & 31;
    const int warp = tid >> 5;
    const int wm   = warp >> 1;       // 0..1
    const int wn   = warp & 1;        // 0..1
    const int m0   = blockIdx.y * 128;
    const int n0   = blockIdx.x * 128;

    const uint32_t sb = smem_u32a(smem);
    const uint32_t* At = Af + (size_t)blockIdx.y * (2 * KT64) * 2048;
    const uint32_t* Bt = Bf + (size_t)blockIdx.x * (2 * KT64) * 2048;

    float acc[4][8][4];
#pragma unroll
    for (int i = 0; i < 4; i++)
#pragma unroll
        for (int j = 0; j < 8; j++)
#pragma unroll
            for (int q = 0; q < 4; q++) acc[i][j][q] = 0.f;

    // ---- prologue: stage k-chunks 0 and 1 into buffers 0 and 1
#pragma unroll
    for (int p = 0; p < 2; p++) {
        const uint32_t boff = (uint32_t)p * 32768u;            // bytes
        const uint32_t* An = At + (size_t)p * 4096;
        const uint32_t* Bn = Bt + (size_t)p * 4096;
#pragma unroll
        for (int i = 0; i < 8; i++) {
            const int s = tid + 128 * i;                       // 0..1023 (uint4)
            CP_ASYNC16(sb + boff + (uint32_t)s * 16,          An + (size_t)s * 4);
            CP_ASYNC16(sb + boff + 16384u + (uint32_t)s * 16, Bn + (size_t)s * 4);
        }
        CP_COMMIT();
    }

    for (int kt = 0; kt < KT64; ++kt) {
        if (kt + 1 < KT64) CP_WAIT1(); else CP_WAIT0();
        __syncthreads();

        // stage chunk kt+2 into buffer (kt+2)%3
        if (kt + 2 < KT64) {
            const int nb3 = (kt + 2) % 3;
            const uint32_t boff = (uint32_t)nb3 * 32768u;
            const uint32_t* An = At + (size_t)(kt + 2) * 4096;
            const uint32_t* Bn = Bt + (size_t)(kt + 2) * 4096;
#pragma unroll
            for (int i = 0; i < 8; i++) {
                const int s = tid + 128 * i;
                CP_ASYNC16(sb + boff + (uint32_t)s * 16,          An + (size_t)s * 4);
                CP_ASYNC16(sb + boff + 16384u + (uint32_t)s * 16, Bn + (size_t)s * 4);
            }
            CP_COMMIT();
        }

        // ---- compute from buffer kt%3: 4 k-steps of 16
        const uint32_t* Asb = smem + (kt % 3) * 8192;
        const uint32_t* Bsb = Asb + 4096;
#pragma unroll
        for (int ks = 0; ks < 4; ++ks) {
            const int tofs = (ks >> 1) * 2048;    // which 128x32 frag tile
            const int ksin = ks & 1;
            uint32_t af[4][4];
            uint32_t bf[8][2];
#pragma unroll
            for (int im = 0; im < 4; ++im) {
                const int mt = wm * 4 + im;
                const uint4 t = *reinterpret_cast<const uint4*>(
                    &Asb[tofs + ((((ksin << 3) + mt) << 5) + lane) * 4]);
                af[im][0] = t.x; af[im][1] = t.y; af[im][2] = t.z; af[im][3] = t.w;
            }
#pragma unroll
            for (int jn = 0; jn < 8; ++jn) {
                const int nt = wn * 8 + jn;
                const uint2 t = *reinterpret_cast<const uint2*>(
                    &Bsb[tofs + ((((ksin << 4) + nt) << 5) + lane) * 2]);
                bf[jn][0] = t.x; bf[jn][1] = t.y;
            }
#pragma unroll
            for (int im = 0; im < 4; ++im)
#pragma unroll
                for (int jn = 0; jn < 8; ++jn)
                    mma16(acc[im][jn], af[im], bf[jn]);
        }
    }

    // ---- epilogue
    const int g = lane >> 2, t = lane & 3;
#pragma unroll
    for (int im = 0; im < 4; ++im) {
        const int mrow = m0 + wm * 64 + im * 16 + g;
#pragma unroll
        for (int jn = 0; jn < 8; ++jn) {
            const int nb = n0 + wn * 64 + jn * 8;
            if (nb < N) {
                if (HALF_OUT) {
                    __half* C = (__half*)Cv;
                    *reinterpret_cast<__half2*>(&C[(size_t)mrow * N + nb + 2 * t]) =
                        __floats2half2_rn(acc[im][jn][0], acc[im][jn][1]);
                    *reinterpret_cast<__half2*>(&C[(size_t)(mrow + 8) * N + nb + 2 * t]) =
                        __floats2half2_rn(acc[im][jn][2], acc[im][jn][3]);
                } else {
                    float* C = (float*)Cv;
                    float2 v0 = make_float2(acc[im][jn][0], acc[im][jn][1]);
                    float2 v1 = make_float2(acc[im][jn][2], acc[im][jn][3]);
                    *reinterpret_cast<float2*>(&C[(size_t)mrow * N + nb + 2 * t])       = v0;
                    *reinterpret_cast<float2*>(&C[(size_t)(mrow + 8) * N + nb + 2 * t]) = v1;
                }
            }
        }
    }
}

// ---------------------------------------------------------------------------
// Preps (unchanged from R13/R15)
// ---------------------------------------------------------------------------
__global__ void __launch_bounds__(256)
prep_frag_a(const float* __restrict__ src, uint32_t* __restrict__ dst, int M, int K)
{
    const int w    = blockIdx.x * 8 + (threadIdx.x >> 5);
    const int lane = threadIdx.x & 31;
    const int TC   = K >> 5;
    const int tile = w >> 4;
    const int slab = w & 15;
    const int tr = tile / TC, tc = tile - tr * TC;
    const int ksin = slab >> 3, mtile = slab & 7;
    const int r0 = tr * 128 + mtile * 16 + (lane >> 2);
    const int c0 = tc * 32 + ksin * 16 + 2 * (lane & 3);

    const float2 v0 = *reinterpret_cast<const float2*>(&src[(size_t)r0 * K + c0]);
    const float2 v1 = *reinterpret_cast<const float2*>(&src[(size_t)(r0 + 8) * K + c0]);
    const float2 v2 = *reinterpret_cast<const float2*>(&src[(size_t)r0 * K + c0 + 8]);
    const float2 v3 = *reinterpret_cast<const float2*>(&src[(size_t)(r0 + 8) * K + c0 + 8]);
    uint4 o;
    o.x = pack_h2(v0.x, v0.y);
    o.y = pack_h2(v1.x, v1.y);
    o.z = pack_h2(v2.x, v2.y);
    o.w = pack_h2(v3.x, v3.y);
    *reinterpret_cast<uint4*>(dst + (size_t)tile * 2048 + slab * 128 + lane * 4) = o;
}

__global__ void __launch_bounds__(256)
prep_frag_b(const float* __restrict__ src, uint32_t* __restrict__ dst,
            int Nr, int K, int Npad)
{
    const int w    = blockIdx.x * 8 + (threadIdx.x >> 5);
    const int lane = threadIdx.x & 31;
    const int TC   = K >> 5;
    const int tile = w >> 5;
    const int slab = w & 31;
    const int tr = tile / TC, tc = tile - tr * TC;
    const int ksin = slab >> 4, ntile = slab & 15;
    const int n0 = tr * 128 + ntile * 8 + (lane >> 2);
    const int c0 = tc * 32 + ksin * 16 + 2 * (lane & 3);

    float2 v0 = make_float2(0.f, 0.f), v1 = make_float2(0.f, 0.f);
    if (n0 < Nr) {
        v0 = *reinterpret_cast<const float2*>(&src[(size_t)n0 * K + c0]);
        v1 = *reinterpret_cast<const float2*>(&src[(size_t)n0 * K + c0 + 8]);
    }
    uint2 o;
    o.x = pack_h2(v0.x, v0.y);
    o.y = pack_h2(v1.x, v1.y);
    *reinterpret_cast<uint2*>(dst + (size_t)tile * 2048 + slab * 64 + lane * 2) = o;
}

// ---------------------------------------------------------------------------
// Elementwise
// ---------------------------------------------------------------------------
__device__ __forceinline__ float siluf(float v)     { return v / (1.f + expf(-v)); }
__device__ __forceinline__ float softplusf(float v) { return fmaxf(v, 0.f) + log1pf(expf(-fabsf(v))); }

// conv+silu, smem-staged, 2 ksteps (32 channels) per block.
// smem slab: 131 rows x 16 u32 (32 fp16 ch), row stride 20 u32 (uint4-aligned,
// conflict-free taps). Block = (tile, kpair); grid = 64*64 = 4096.
__global__ void __launch_bounds__(256)
conv_silu_kernel(const __half* __restrict__ xz, const float* __restrict__ cw,
                 const float* __restrict__ cb, uint32_t* __restrict__ xcf)
{
    __shared__ uint32_t sx[131 * 20];
    const int tid   = threadIdx.x;
    const int tile  = blockIdx.x >> 6;          // 0..63
    const int kpair = blockIdx.x & 63;          // 2 ksteps = 32 channels
    const int cbase = kpair * 32;
    const int base_row = tile * 128;
    const bool batch_start = (base_row & (LSEQ - 1)) == 0;

    // cooperative load: 131 rows x 4 uint4 (64 B of fp16 channels per row)
    for (int i = tid; i < 131 * 4; i += 256) {
        const int s = i >> 2;           // smem row
        const int q = i & 3;            // uint4 within row
        uint4 v = make_uint4(0u, 0u, 0u, 0u);
        const int g = base_row + s - 3;
        if (s >= 3 || !batch_start) {
            v = *reinterpret_cast<const uint4*>(
                &xz[(size_t)g * NXZ + cbase + q * 8]);
        }
        *reinterpret_cast<uint4*>(&sx[s * 20 + q * 4]) = v;
    }
    __syncthreads();

    // compute: warp = mtile; each thread produces 2 uint4 slots (ksl 0,1)
    const int warp = tid >> 5, lane = tid & 31;
    const int mtile = warp;
    const int rr0 = mtile * 16 + (lane >> 2);
    const int cl  = 2 * (lane & 3);

#pragma unroll
    for (int ksl = 0; ksl < 2; ++ksl) {
        const int cg = cbase + ksl * 16 + cl;    // global channel base
        const int w0 = ksl * 8 + (cl >> 1);      // smem word for (cg, cg+1)

        float wt0[4], wt1[4], wt2[4], wt3[4];
        const float b0 = cb[cg], b1 = cb[cg + 1], b2 = cb[cg + 8], b3 = cb[cg + 9];
#pragma unroll
        for (int k = 0; k < 4; k++) {
            wt0[k] = cw[(cg + 0) * 4 + k];
            wt1[k] = cw[(cg + 1) * 4 + k];
            wt2[k] = cw[(cg + 8) * 4 + k];
            wt3[k] = cw[(cg + 9) * 4 + k];
        }

        uint4 o;
#pragma unroll
        for (int half = 0; half < 2; half++) {
            const int r = rr0 + half * 8;
            float a0 = b0, a1 = b1, a2 = b2, a3 = b3;
#pragma unroll
            for (int k = 0; k < 4; k++) {
                const float2 f0 = __half22float2(
                    *reinterpret_cast<const __half2*>(&sx[(r + k) * 20 + w0]));
                const float2 f1 = __half22float2(
                    *reinterpret_cast<const __half2*>(&sx[(r + k) * 20 + w0 + 4]));
                a0 = fmaf(wt0[k], f0.x, a0);
                a1 = fmaf(wt1[k], f0.y, a1);
                a2 = fmaf(wt2[k], f1.x, a2);
                a3 = fmaf(wt3[k], f1.y, a3);
            }
            const uint32_t lo = pack_h2(siluf(a0), siluf(a1));
            const uint32_t hi = pack_h2(siluf(a2), siluf(a3));
            if (half == 0) { o.x = lo; o.z = hi; }
            else           { o.y = lo; o.w = hi; }
        }

        const int kstep = kpair * 2 + ksl;
        uint32_t* d = xcf + (size_t)(tile * (DINNER >> 5) + kpair) * 2048
                          + ((ksl * 8 + mtile) * 32 + lane) * 4;
        (void)kstep;
        *reinterpret_cast<uint4*>(d) = o;
    }
}

// combine (unchanged from R15)
__device__ __forceinline__ uint32_t comb_pair(
    const __half* __restrict__ xz, const __half* __restrict__ proj,
    const float* __restrict__ D, int row, int c, float bc, uint32_t xc2)
{
    const float2 dp = __half22float2(
        *reinterpret_cast<const __half2*>(&proj[(size_t)row * NPROJ + 2 * D_STATE + c]));
    const float2 z  = __half22float2(
        *reinterpret_cast<const __half2*>(&xz[(size_t)row * NXZ + DINNER + c]));
    const float2 Dv = *reinterpret_cast<const float2*>(&D[c]);
    const __half2 xh = *reinterpret_cast<const __half2*>(&xc2);
    const float y0 = (softplusf(dp.x) * bc + Dv.x) * __low2float(xh)  * siluf(z.x);
    const float y1 = (softplusf(dp.y) * bc + Dv.y) * __high2float(xh) * siluf(z.y);
    return pack_h2(y0, y1);
}

__global__ void __launch_bounds__(256)
combine_kernel(const __half* __restrict__ xz, const uint32_t* __restrict__ xcf,
               const __half* __restrict__ proj, const float* __restrict__ D,
               uint32_t* __restrict__ yf)
{
    __shared__ float sbc[128];
    const int tile = blockIdx.x >> 4;
    const int kgrp = blockIdx.x & 15;
    const int tid  = threadIdx.x;

    if (tid < 128) {
        const __half* pr = proj + (size_t)(tile * 128 + tid) * NPROJ;
        float v = 0.f;
#pragma unroll
        for (int s = 0; s < D_STATE; s++)
            v = fmaf(__half2float(pr[s]), __half2float(pr[D_STATE + s]), v);
        sbc[tid] = v;
    }
    __syncthreads();

    const int warp = tid >> 5, lane = tid & 31;
#pragma unroll
    for (int i = 0; i < 8; i++) {
        const int slab  = warp * 8 + i;
        const int ks    = kgrp * 8 + (slab >> 3);
        const int mtile = slab & 7;
        const int rr0   = mtile * 16 + (lane >> 2);
        const int r0    = tile * 128 + rr0;
        const int c0    = ks * 16 + 2 * (lane & 3);
        const size_t base = (size_t)(tile * (DINNER >> 5) + (ks >> 1)) * 2048
                          + (((ks & 1) * 8 + mtile) * 32 + lane) * 4;
        const uint4 xin = *reinterpret_cast<const uint4*>(xcf + base);
        const float bc0 = sbc[rr0], bc1 = sbc[rr0 + 8];
        uint4 o;
        o.x = comb_pair(xz, proj, D, r0,     c0,     bc0, xin.x);
        o.y = comb_pair(xz, proj, D, r0 + 8, c0,     bc1, xin.y);
        o.z = comb_pair(xz, proj, D, r0,     c0 + 8, bc0, xin.z);
        o.w = comb_pair(xz, proj, D, r0 + 8, c0 + 8, bc1, xin.w);
        *reinterpret_cast<uint4*>(yf + base) = o;
    }
}

// ---------------------------------------------------------------------------
// Launch
// ---------------------------------------------------------------------------
extern "C" void kernel_launch(void* const* d_in, const int* in_sizes, int n_in,
                              void* d_out, int out_size)
{
    const float* x      = (const float*)d_in[0];
    const float* W_in   = (const float*)d_in[1];
    const float* conv_w = (const float*)d_in[2];
    const float* conv_b = (const float*)d_in[3];
    const float* W_xp   = (const float*)d_in[4];
    const float* D      = (const float*)d_in[5];
    const float* W_out  = (const float*)d_in[6];
    float* out = (float*)d_out;

    void *p_xz, *p_proj, *p_xf, *p_winf, *p_xcf, *p_wxpf, *p_yf, *p_woutf;
    cudaGetSymbolAddress(&p_xz,    g_xz);
    cudaGetSymbolAddress(&p_proj,  g_proj);
    cudaGetSymbolAddress(&p_xf,    g_xf);
    cudaGetSymbolAddress(&p_winf,  g_winf);
    cudaGetSymbolAddress(&p_xcf,   g_xcf);
    cudaGetSymbolAddress(&p_wxpf,  g_wxpf);
    cudaGetSymbolAddress(&p_yf,    g_yf);
    cudaGetSymbolAddress(&p_woutf, g_woutf);

    cudaFuncSetAttribute(gemm_f16<true>,  cudaFuncAttributeMaxDynamicSharedMemorySize, 98304);
    cudaFuncSetAttribute(gemm_f16<false>, cudaFuncAttributeMaxDynamicSharedMemorySize, 98304);

    // Preps just-before-use
    prep_frag_a<<<4096, 256>>>(x, (uint32_t*)p_xf, NROWS, DMODEL);
    prep_frag_b<<<4096, 256>>>(W_in, (uint32_t*)p_winf, NXZ, DMODEL, NXZ);

    // GEMM1: xz = x @ W_in^T   (8192 x 4096 x 1024), fp16 output, KT64=16
    gemm_f16<true><<<dim3(NXZ / 128, NROWS / 128), 128, 98304>>>(
        (const uint32_t*)p_xf, (const uint32_t*)p_winf, p_xz,
        NROWS, NXZ, DMODEL / 64);

    // conv + SiLU -> xc (fragment layout): 64 tiles x 64 kpairs
    conv_silu_kernel<<<4096, 256>>>(
        (const __half*)p_xz, conv_w, conv_b, (uint32_t*)p_xcf);

    prep_frag_b<<<4352, 256>>>(W_xp, (uint32_t*)p_wxpf, NPROJ, DINNER, NPROJ_PAD);

    // GEMM2: proj = xc @ W_xproj^T  (8192 x 2080 x 2048), fp16 output, KT64=32
    gemm_f16<true><<<dim3(NPROJ_PAD / 128, NROWS / 128), 128, 98304>>>(
        (const uint32_t*)p_xcf, (const uint32_t*)p_wxpf, p_proj,
        NROWS, NPROJ, DINNER / 64);

    // combine -> y (fragment layout)
    combine_kernel<<<1024, 256>>>(
        (const __half*)p_xz, (const uint32_t*)p_xcf, (const __half*)p_proj, D,
        (uint32_t*)p_yf);

    prep_frag_b<<<2048, 256>>>(W_out, (uint32_t*)p_woutf, DMODEL, DINNER, DMODEL);

    // GEMM3: out = y @ W_out^T   (8192 x 1024 x 2048), fp32 output, KT64=32
    gemm_f16<false><<<dim3(DMODEL / 128, NROWS / 128), 128, 98304>>>(
        (const uint32_t*)p_yf, (const uint32_t*)p_woutf, out,
        NROWS, DMODEL, DINNER / 64);
}

// round 17
// speedup vs baseline: 1.2618x; 1.0218x over previous
#include <cuda_runtime.h>
#include <cuda_fp16.h>
#include <cstdint>

// ---------------------------------------------------------------------------
// SelectiveSSM on GB300 (base sm_103 target => mma.sync path).
// R17 over passing R16 (523.7 us):
//   1. GEMM reverted to the best-measured R15 config (BK=32, 4x16KB pipeline,
//      2 CTA/SM) — BK=64 measured slightly negative.
//   2. conv_silu: 4 ksteps (64 ch) per block, stride-36 smem (conflict-free),
//      2048 blocks — conv is issue-bound, fewer blocks/barriers/halo loads.
//   3. All four prep kernels fused into ONE launch (blockIdx-range dispatch)
//      — removes 3 launch gaps + tail waves.
// Combine byte-identical to R15/R16.
// ---------------------------------------------------------------------------

#define D_STATE 16
#define BSZ     2
#define LSEQ    4096
#define DMODEL  1024
#define DINNER  2048
#define NROWS   (BSZ * LSEQ)            // 8192
#define NXZ     (2 * DINNER)            // 4096
#define NPROJ   (2 * D_STATE + DINNER)  // 2080
#define NPROJ_PAD 2176                  // 17 * 128

// Scratch (device globals: allocation-free)
__device__ __half g_xz[NROWS * (size_t)NXZ];       // GEMM1 out (fp16)
__device__ __half g_proj[NROWS * (size_t)NPROJ];   // GEMM2 out (fp16)
// fragment-major fp16 operands (u32 = packed half2)
__device__ uint32_t g_xf[NROWS * (size_t)DMODEL / 2];
__device__ uint32_t g_winf[NXZ * (size_t)DMODEL / 2];
__device__ uint32_t g_xcf[NROWS * (size_t)DINNER / 2];
__device__ uint32_t g_wxpf[NPROJ_PAD * (size_t)DINNER / 2];
__device__ uint32_t g_yf[NROWS * (size_t)DINNER / 2];
__device__ uint32_t g_woutf[DMODEL * (size_t)DINNER / 2];

// ---------------------------------------------------------------------------
// fp16 fragment layout, per 128(row) x 32(k) tile = 2048 u32 (8 KB).
// A-slot (uint4) at (ksin, mtile, lane): r0 = mtile*16 + (lane>>2),
//   c0 = ksin*16 + 2*(lane&3); regs = (r0,c0)(r0+8,c0)(r0,c0+8)(r0+8,c0+8).
// B-slot (uint2): n0 = ntile*8 + (lane>>2); regs = (n0,c0)(n0,c0+8).
// ---------------------------------------------------------------------------

__device__ __forceinline__ uint32_t pack_h2(float lo, float hi) {
    __half2 h = __floats2half2_rn(lo, hi);
    return *reinterpret_cast<uint32_t*>(&h);
}

__device__ __forceinline__ void mma16(float acc[4], const uint32_t a[4], const uint32_t b[2]) {
    asm volatile(
        "mma.sync.aligned.m16n8k16.row.col.f32.f16.f16.f32 "
        "{%0,%1,%2,%3}, {%4,%5,%6,%7}, {%8,%9}, {%0,%1,%2,%3};"
        : "+f"(acc[0]), "+f"(acc[1]), "+f"(acc[2]), "+f"(acc[3])
        : "r"(a[0]), "r"(a[1]), "r"(a[2]), "r"(a[3]), "r"(b[0]), "r"(b[1]));
}

#define CP_ASYNC16(dst_u32, src_ptr) \
    asm volatile("cp.async.cg.shared.global [%0], [%1], 16;" \
                 :: "r"(dst_u32), "l"(src_ptr) : "memory")
#define CP_COMMIT() asm volatile("cp.async.commit_group;" ::: "memory")
#define CP_WAIT0()  asm volatile("cp.async.wait_group 0;" ::: "memory")
#define CP_WAIT1()  asm volatile("cp.async.wait_group 1;" ::: "memory")
#define CP_WAIT2()  asm volatile("cp.async.wait_group 2;" ::: "memory")

__device__ __forceinline__ uint32_t smem_u32a(const void* p) {
    uint32_t a;
    asm("{ .reg .u64 t; cvta.to.shared.u64 t, %1; cvt.u32.u64 %0, t; }"
        : "=r"(a) : "l"(p));
    return a;
}

// ---------------------------------------------------------------------------
// fp16 GEMM — byte-identical to passing R15 (BK=32, proven best).
// CTA 128x128, 128 threads, warp grid 2x2, warp tile 64x64.
// smem: 4 buffers x 16 KB = 64 KB dynamic. 2 CTA/SM. 4-stage pipeline.
// ---------------------------------------------------------------------------
template<bool HALF_OUT>
__global__ void __launch_bounds__(128, 2)
gemm_f16(const uint32_t* __restrict__ Af, const uint32_t* __restrict__ Bf,
         void* __restrict__ Cv, int M, int N, int KT /* = K/32 */)
{
    extern __shared__ uint32_t smem[];   // 4 x 4096 u32
    const int tid  = threadIdx.x;
    const int lane = tid & 31;
    const int warp = tid >> 5;
    const int wm   = warp >> 1;       // 0..1
    const int wn   = warp & 1;        // 0..1
    const int m0   = blockIdx.y * 128;
    const int n0   = blockIdx.x * 128;

    const uint32_t sb = smem_u32a(smem);
    const uint32_t* At = Af + (size_t)blockIdx.y * KT * 2048;
    const uint32_t* Bt = Bf + (size_t)blockIdx.x * KT * 2048;

    float acc[4][8][4];
#pragma unroll
    for (int i = 0; i < 4; i++)
#pragma unroll
        for (int j = 0; j < 8; j++)
#pragma unroll
            for (int q = 0; q < 4; q++) acc[i][j][q] = 0.f;

    // ---- prologue: stage tiles 0..2 into buffers 0..2 (stage-ahead 3)
#pragma unroll
    for (int p = 0; p < 3; p++) {
        if (p < KT) {
            const uint32_t boff = (uint32_t)p * 16384u;
            const uint32_t* An = At + (size_t)p * 2048;
            const uint32_t* Bn = Bt + (size_t)p * 2048;
#pragma unroll
            for (int i = 0; i < 4; i++) {
                const int s = tid + 128 * i;
                CP_ASYNC16(sb + boff + (uint32_t)s * 16,         An + (size_t)s * 4);
                CP_ASYNC16(sb + boff + 8192u + (uint32_t)s * 16, Bn + (size_t)s * 4);
            }
            CP_COMMIT();
        }
    }

    for (int kt = 0; kt < KT; ++kt) {
        const int remaining = KT - 1 - kt;
        if (remaining >= 2)      CP_WAIT2();
        else if (remaining == 1) CP_WAIT1();
        else                     CP_WAIT0();
        __syncthreads();

        if (kt + 3 < KT) {
            const uint32_t boff = (uint32_t)((kt + 3) & 3) * 16384u;
            const uint32_t* An = At + (size_t)(kt + 3) * 2048;
            const uint32_t* Bn = Bt + (size_t)(kt + 3) * 2048;
#pragma unroll
            for (int i = 0; i < 4; i++) {
                const int s = tid + 128 * i;
                CP_ASYNC16(sb + boff + (uint32_t)s * 16,         An + (size_t)s * 4);
                CP_ASYNC16(sb + boff + 8192u + (uint32_t)s * 16, Bn + (size_t)s * 4);
            }
            CP_COMMIT();
        }

        const uint32_t* Asb = smem + (kt & 3) * 4096;
        const uint32_t* Bsb = Asb + 2048;
#pragma unroll
        for (int ks = 0; ks < 2; ++ks) {
            uint32_t af[4][4];
            uint32_t bf[8][2];
#pragma unroll
            for (int im = 0; im < 4; ++im) {
                const int mt = wm * 4 + im;
                const uint4 t = *reinterpret_cast<const uint4*>(
                    &Asb[((((ks << 3) + mt) << 5) + lane) * 4]);
                af[im][0] = t.x; af[im][1] = t.y; af[im][2] = t.z; af[im][3] = t.w;
            }
#pragma unroll
            for (int jn = 0; jn < 8; ++jn) {
                const int nt = wn * 8 + jn;
                const uint2 t = *reinterpret_cast<const uint2*>(
                    &Bsb[((((ks << 4) + nt) << 5) + lane) * 2]);
                bf[jn][0] = t.x; bf[jn][1] = t.y;
            }
#pragma unroll
            for (int im = 0; im < 4; ++im)
#pragma unroll
                for (int jn = 0; jn < 8; ++jn)
                    mma16(acc[im][jn], af[im], bf[jn]);
        }
    }

    // ---- epilogue
    const int g = lane >> 2, t = lane & 3;
#pragma unroll
    for (int im = 0; im < 4; ++im) {
        const int mrow = m0 + wm * 64 + im * 16 + g;
#pragma unroll
        for (int jn = 0; jn < 8; ++jn) {
            const int nb = n0 + wn * 64 + jn * 8;
            if (nb < N) {
                if (HALF_OUT) {
                    __half* C = (__half*)Cv;
                    *reinterpret_cast<__half2*>(&C[(size_t)mrow * N + nb + 2 * t]) =
                        __floats2half2_rn(acc[im][jn][0], acc[im][jn][1]);
                    *reinterpret_cast<__half2*>(&C[(size_t)(mrow + 8) * N + nb + 2 * t]) =
                        __floats2half2_rn(acc[im][jn][2], acc[im][jn][3]);
                } else {
                    float* C = (float*)Cv;
                    float2 v0 = make_float2(acc[im][jn][0], acc[im][jn][1]);
                    float2 v1 = make_float2(acc[im][jn][2], acc[im][jn][3]);
                    *reinterpret_cast<float2*>(&C[(size_t)mrow * N + nb + 2 * t])       = v0;
                    *reinterpret_cast<float2*>(&C[(size_t)(mrow + 8) * N + nb + 2 * t]) = v1;
                }
            }
        }
    }
}

// ---------------------------------------------------------------------------
// Fused prep: one launch does all four fragment permutes.
// Block ranges: [0,4096) prep_a(x); [4096,8192) prep_b(W_in);
//               [8192,12544) prep_b(W_xp); [12544,14592) prep_b(W_out).
// ---------------------------------------------------------------------------
__device__ __forceinline__ void prep_a_body(
    const float* __restrict__ src, uint32_t* __restrict__ dst,
    int K, int w, int lane)
{
    const int TC   = K >> 5;
    const int tile = w >> 4;
    const int slab = w & 15;
    const int tr = tile / TC, tc = tile - tr * TC;
    const int ksin = slab >> 3, mtile = slab & 7;
    const int r0 = tr * 128 + mtile * 16 + (lane >> 2);
    const int c0 = tc * 32 + ksin * 16 + 2 * (lane & 3);

    const float2 v0 = *reinterpret_cast<const float2*>(&src[(size_t)r0 * K + c0]);
    const float2 v1 = *reinterpret_cast<const float2*>(&src[(size_t)(r0 + 8) * K + c0]);
    const float2 v2 = *reinterpret_cast<const float2*>(&src[(size_t)r0 * K + c0 + 8]);
    const float2 v3 = *reinterpret_cast<const float2*>(&src[(size_t)(r0 + 8) * K + c0 + 8]);
    uint4 o;
    o.x = pack_h2(v0.x, v0.y);
    o.y = pack_h2(v1.x, v1.y);
    o.z = pack_h2(v2.x, v2.y);
    o.w = pack_h2(v3.x, v3.y);
    *reinterpret_cast<uint4*>(dst + (size_t)tile * 2048 + slab * 128 + lane * 4) = o;
}

__device__ __forceinline__ void prep_b_body(
    const float* __restrict__ src, uint32_t* __restrict__ dst,
    int Nr, int K, int w, int lane)
{
    const int TC   = K >> 5;
    const int tile = w >> 5;
    const int slab = w & 31;
    const int tr = tile / TC, tc = tile - tr * TC;
    const int ksin = slab >> 4, ntile = slab & 15;
    const int n0 = tr * 128 + ntile * 8 + (lane >> 2);
    const int c0 = tc * 32 + ksin * 16 + 2 * (lane & 3);

    float2 v0 = make_float2(0.f, 0.f), v1 = make_float2(0.f, 0.f);
    if (n0 < Nr) {
        v0 = *reinterpret_cast<const float2*>(&src[(size_t)n0 * K + c0]);
        v1 = *reinterpret_cast<const float2*>(&src[(size_t)n0 * K + c0 + 8]);
    }
    uint2 o;
    o.x = pack_h2(v0.x, v0.y);
    o.y = pack_h2(v1.x, v1.y);
    *reinterpret_cast<uint2*>(dst + (size_t)tile * 2048 + slab * 64 + lane * 2) = o;
}

__global__ void __launch_bounds__(256)
prep_all(const float* __restrict__ x,    const float* __restrict__ W_in,
         const float* __restrict__ W_xp, const float* __restrict__ W_out,
         uint32_t* __restrict__ xf,   uint32_t* __restrict__ winf,
         uint32_t* __restrict__ wxpf, uint32_t* __restrict__ woutf)
{
    const int lane = threadIdx.x & 31;
    const int bid  = blockIdx.x;
    if (bid < 4096) {
        const int w = bid * 8 + (threadIdx.x >> 5);
        prep_a_body(x, xf, DMODEL, w, lane);
    } else if (bid < 8192) {
        const int w = (bid - 4096) * 8 + (threadIdx.x >> 5);
        prep_b_body(W_in, winf, NXZ, DMODEL, w, lane);
    } else if (bid < 12544) {
        const int w = (bid - 8192) * 8 + (threadIdx.x >> 5);
        prep_b_body(W_xp, wxpf, NPROJ, DINNER, w, lane);
    } else {
        const int w = (bid - 12544) * 8 + (threadIdx.x >> 5);
        prep_b_body(W_out, woutf, DMODEL, DINNER, w, lane);
    }
}

// ---------------------------------------------------------------------------
// Elementwise
// ---------------------------------------------------------------------------
__device__ __forceinline__ float siluf(float v)     { return v / (1.f + expf(-v)); }
__device__ __forceinline__ float softplusf(float v) { return fmaxf(v, 0.f) + log1pf(expf(-fabsf(v))); }

// conv+silu, smem-staged, 4 ksteps (64 channels) per block.
// smem slab: 131 rows x 32 u32 (64 fp16 ch), row stride 36 u32 (uint4-aligned;
// banks: (4r + w) mod 32 distinct over q=0..7, w=0..3 -> conflict-free).
// Block = (tile, kquad); grid = 64*32 = 2048.
__global__ void __launch_bounds__(256)
conv_silu_kernel(const __half* __restrict__ xz, const float* __restrict__ cw,
                 const float* __restrict__ cb, uint32_t* __restrict__ xcf)
{
    __shared__ uint32_t sx[131 * 36];
    const int tid   = threadIdx.x;
    const int tile  = blockIdx.x >> 5;          // 0..63
    const int kquad = blockIdx.x & 31;          // 4 ksteps = 64 channels
    const int cbase = kquad * 64;
    const int base_row = tile * 128;
    const bool batch_start = (base_row & (LSEQ - 1)) == 0;

    // cooperative load: 131 rows x 8 uint4 (128 B of fp16 channels per row)
    for (int i = tid; i < 131 * 8; i += 256) {
        const int s = i >> 3;           // smem row
        const int q = i & 7;            // uint4 within row
        uint4 v = make_uint4(0u, 0u, 0u, 0u);
        const int g = base_row + s - 3;
        if (s >= 3 || !batch_start) {
            v = *reinterpret_cast<const uint4*>(
                &xz[(size_t)g * NXZ + cbase + q * 8]);
        }
        *reinterpret_cast<uint4*>(&sx[s * 36 + q * 4]) = v;
    }
    __syncthreads();

    // compute: warp = mtile; each thread produces 4 uint4 slots (ksl 0..3)
    const int warp = tid >> 5, lane = tid & 31;
    const int mtile = warp;
    const int rr0 = mtile * 16 + (lane >> 2);
    const int cl  = 2 * (lane & 3);

#pragma unroll
    for (int ksl = 0; ksl < 4; ++ksl) {
        const int cg = cbase + ksl * 16 + cl;    // global channel base
        const int w0 = ksl * 8 + (cl >> 1);      // smem word for (cg, cg+1)

        float wt0[4], wt1[4], wt2[4], wt3[4];
        const float b0 = cb[cg], b1 = cb[cg + 1], b2 = cb[cg + 8], b3 = cb[cg + 9];
#pragma unroll
        for (int k = 0; k < 4; k++) {
            wt0[k] = cw[(cg + 0) * 4 + k];
            wt1[k] = cw[(cg + 1) * 4 + k];
            wt2[k] = cw[(cg + 8) * 4 + k];
            wt3[k] = cw[(cg + 9) * 4 + k];
        }

        uint4 o;
#pragma unroll
        for (int half = 0; half < 2; half++) {
            const int r = rr0 + half * 8;
            float a0 = b0, a1 = b1, a2 = b2, a3 = b3;
#pragma unroll
            for (int k = 0; k < 4; k++) {
                const float2 f0 = __half22float2(
                    *reinterpret_cast<const __half2*>(&sx[(r + k) * 36 + w0]));
                const float2 f1 = __half22float2(
                    *reinterpret_cast<const __half2*>(&sx[(r + k) * 36 + w0 + 4]));
                a0 = fmaf(wt0[k], f0.x, a0);
                a1 = fmaf(wt1[k], f0.y, a1);
                a2 = fmaf(wt2[k], f1.x, a2);
                a3 = fmaf(wt3[k], f1.y, a3);
            }
            const uint32_t lo = pack_h2(siluf(a0), siluf(a1));
            const uint32_t hi = pack_h2(siluf(a2), siluf(a3));
            if (half == 0) { o.x = lo; o.z = hi; }
            else           { o.y = lo; o.w = hi; }
        }

        const int kstep = kquad * 4 + ksl;
        uint32_t* d = xcf + (size_t)(tile * (DINNER >> 5) + (kstep >> 1)) * 2048
                          + (((kstep & 1) * 8 + mtile) * 32 + lane) * 4;
        *reinterpret_cast<uint4*>(d) = o;
    }
}

// combine (unchanged from R15/R16)
__device__ __forceinline__ uint32_t comb_pair(
    const __half* __restrict__ xz, const __half* __restrict__ proj,
    const float* __restrict__ D, int row, int c, float bc, uint32_t xc2)
{
    const float2 dp = __half22float2(
        *reinterpret_cast<const __half2*>(&proj[(size_t)row * NPROJ + 2 * D_STATE + c]));
    const float2 z  = __half22float2(
        *reinterpret_cast<const __half2*>(&xz[(size_t)row * NXZ + DINNER + c]));
    const float2 Dv = *reinterpret_cast<const float2*>(&D[c]);
    const __half2 xh = *reinterpret_cast<const __half2*>(&xc2);
    const float y0 = (softplusf(dp.x) * bc + Dv.x) * __low2float(xh)  * siluf(z.x);
    const float y1 = (softplusf(dp.y) * bc + Dv.y) * __high2float(xh) * siluf(z.y);
    return pack_h2(y0, y1);
}

__global__ void __launch_bounds__(256)
combine_kernel(const __half* __restrict__ xz, const uint32_t* __restrict__ xcf,
               const __half* __restrict__ proj, const float* __restrict__ D,
               uint32_t* __restrict__ yf)
{
    __shared__ float sbc[128];
    const int tile = blockIdx.x >> 4;
    const int kgrp = blockIdx.x & 15;
    const int tid  = threadIdx.x;

    if (tid < 128) {
        const __half* pr = proj + (size_t)(tile * 128 + tid) * NPROJ;
        float v = 0.f;
#pragma unroll
        for (int s = 0; s < D_STATE; s++)
            v = fmaf(__half2float(pr[s]), __half2float(pr[D_STATE + s]), v);
        sbc[tid] = v;
    }
    __syncthreads();

    const int warp = tid >> 5, lane = tid & 31;
#pragma unroll
    for (int i = 0; i < 8; i++) {
        const int slab  = warp * 8 + i;
        const int ks    = kgrp * 8 + (slab >> 3);
        const int mtile = slab & 7;
        const int rr0   = mtile * 16 + (lane >> 2);
        const int r0    = tile * 128 + rr0;
        const int c0    = ks * 16 + 2 * (lane & 3);
        const size_t base = (size_t)(tile * (DINNER >> 5) + (ks >> 1)) * 2048
                          + (((ks & 1) * 8 + mtile) * 32 + lane) * 4;
        const uint4 xin = *reinterpret_cast<const uint4*>(xcf + base);
        const float bc0 = sbc[rr0], bc1 = sbc[rr0 + 8];
        uint4 o;
        o.x = comb_pair(xz, proj, D, r0,     c0,     bc0, xin.x);
        o.y = comb_pair(xz, proj, D, r0 + 8, c0,     bc1, xin.y);
        o.z = comb_pair(xz, proj, D, r0,     c0 + 8, bc0, xin.z);
        o.w = comb_pair(xz, proj, D, r0 + 8, c0 + 8, bc1, xin.w);
        *reinterpret_cast<uint4*>(yf + base) = o;
    }
}

// ---------------------------------------------------------------------------
// Launch
// ---------------------------------------------------------------------------
extern "C" void kernel_launch(void* const* d_in, const int* in_sizes, int n_in,
                              void* d_out, int out_size)
{
    const float* x      = (const float*)d_in[0];
    const float* W_in   = (const float*)d_in[1];
    const float* conv_w = (const float*)d_in[2];
    const float* conv_b = (const float*)d_in[3];
    const float* W_xp   = (const float*)d_in[4];
    const float* D      = (const float*)d_in[5];
    const float* W_out  = (const float*)d_in[6];
    float* out = (float*)d_out;

    void *p_xz, *p_proj, *p_xf, *p_winf, *p_xcf, *p_wxpf, *p_yf, *p_woutf;
    cudaGetSymbolAddress(&p_xz,    g_xz);
    cudaGetSymbolAddress(&p_proj,  g_proj);
    cudaGetSymbolAddress(&p_xf,    g_xf);
    cudaGetSymbolAddress(&p_winf,  g_winf);
    cudaGetSymbolAddress(&p_xcf,   g_xcf);
    cudaGetSymbolAddress(&p_wxpf,  g_wxpf);
    cudaGetSymbolAddress(&p_yf,    g_yf);
    cudaGetSymbolAddress(&p_woutf, g_woutf);

    cudaFuncSetAttribute(gemm_f16<true>,  cudaFuncAttributeMaxDynamicSharedMemorySize, 65536);
    cudaFuncSetAttribute(gemm_f16<false>, cudaFuncAttributeMaxDynamicSharedMemorySize, 65536);

    // One fused prep launch: x, W_in, W_xp, W_out -> fragment layout
    prep_all<<<14592, 256>>>(x, W_in, W_xp, W_out,
                             (uint32_t*)p_xf, (uint32_t*)p_winf,
                             (uint32_t*)p_wxpf, (uint32_t*)p_woutf);

    // GEMM1: xz = x @ W_in^T   (8192 x 4096 x 1024), fp16 output
    gemm_f16<true><<<dim3(NXZ / 128, NROWS / 128), 128, 65536>>>(
        (const uint32_t*)p_xf, (const uint32_t*)p_winf, p_xz,
        NROWS, NXZ, DMODEL / 32);

    // conv + SiLU -> xc (fragment layout): 64 tiles x 32 kquads
    conv_silu_kernel<<<2048, 256>>>(
        (const __half*)p_xz, conv_w, conv_b, (uint32_t*)p_xcf);

    // GEMM2: proj = xc @ W_xproj^T  (8192 x 2080 x 2048), fp16 output
    gemm_f16<true><<<dim3(NPROJ_PAD / 128, NROWS / 128), 128, 65536>>>(
        (const uint32_t*)p_xcf, (const uint32_t*)p_wxpf, p_proj,
        NROWS, NPROJ, DINNER / 32);

    // combine -> y (fragment layout)
    combine_kernel<<<1024, 256>>>(
        (const __half*)p_xz, (const uint32_t*)p_xcf, (const __half*)p_proj, D,
        (uint32_t*)p_yf);

    // GEMM3: out = y @ W_out^T   (8192 x 1024 x 2048), fp32 output
    gemm_f16<false><<<dim3(DMODEL / 128, NROWS / 128), 128, 65536>>>(
        (const uint32_t*)p_yf, (const uint32_t*)p_woutf, out,
        NROWS, DMODEL, DINNER / 32);
}